// round 14
// baseline (speedup 1.0000x reference)
#include <cuda_runtime.h>
#include <cuda_fp16.h>
#include <cstdint>

#define EMBED 1024
#define HEAD  128
#define BATCH 4
#define SEQ   4096
#define BS    (BATCH*SEQ)
#define QSCALE 0.04508422f   // (1/sqrt(1024)) * log2(e)

// ---------------------------------------------------------------------------
// Global scratch (q prescaled by QSCALE at proj epilogue)
// ---------------------------------------------------------------------------
__device__ __align__(256) __half g_x[BS*EMBED];
__device__ __align__(256) __half g_w[3*EMBED*HEAD];
__device__ __align__(256) __half g_q[BS*HEAD], g_k[BS*HEAD], g_v[BS*HEAD];
__device__ __align__(256) float g_l[BS];

// ---------------------------------------------------------------------------
// helpers
// ---------------------------------------------------------------------------
__device__ __forceinline__ uint32_t smem_u32(const void* p) {
    uint32_t a;
    asm("{ .reg .u64 t; cvta.to.shared.u64 t, %1; cvt.u32.u64 %0, t; }" : "=r"(a) : "l"(p));
    return a;
}
__device__ __forceinline__ uint32_t sidx(int row, int cb, int rb) {
    return (uint32_t)(row*rb + ((((cb >> 4) ^ (row & 7)) << 4) | (cb & 15)));
}
__device__ __forceinline__ void cpa(uint32_t d, const void* s) {
    asm volatile("cp.async.cg.shared.global [%0], [%1], 16;" :: "r"(d), "l"(s));
}
#define CP_COMMIT() asm volatile("cp.async.commit_group;" ::: "memory")
#define CP_WAIT0()  asm volatile("cp.async.wait_group 0;" ::: "memory")

__device__ __forceinline__ void ldsm4(uint32_t* r, uint32_t a) {
    asm volatile("ldmatrix.sync.aligned.m8n8.x4.shared.b16 {%0,%1,%2,%3}, [%4];"
        : "=r"(r[0]), "=r"(r[1]), "=r"(r[2]), "=r"(r[3]) : "r"(a));
}
__device__ __forceinline__ void ldsm4t(uint32_t* r, uint32_t a) {
    asm volatile("ldmatrix.sync.aligned.m8n8.x4.trans.shared.b16 {%0,%1,%2,%3}, [%4];"
        : "=r"(r[0]), "=r"(r[1]), "=r"(r[2]), "=r"(r[3]) : "r"(a));
}
__device__ __forceinline__ void mma16816(float* d, const uint32_t* a, const uint32_t* b) {
    asm volatile("mma.sync.aligned.m16n8k16.row.col.f32.f16.f16.f32 "
        "{%0,%1,%2,%3}, {%4,%5,%6,%7}, {%8,%9}, {%0,%1,%2,%3};"
        : "+f"(d[0]), "+f"(d[1]), "+f"(d[2]), "+f"(d[3])
        : "r"(a[0]), "r"(a[1]), "r"(a[2]), "r"(a[3]), "r"(b[0]), "r"(b[1]));
}
__device__ __forceinline__ void mma16816h(uint32_t* d, const uint32_t* a, const uint32_t* b) {
    asm volatile("mma.sync.aligned.m16n8k16.row.col.f16.f16.f16.f16 "
        "{%0,%1}, {%2,%3,%4,%5}, {%6,%7}, {%0,%1};"
        : "+r"(d[0]), "+r"(d[1])
        : "r"(a[0]), "r"(a[1]), "r"(a[2]), "r"(a[3]), "r"(b[0]), "r"(b[1]));
}
__device__ __forceinline__ uint32_t packh2(float a, float b) {
    __half2 h = __floats2half2_rn(a, b);
    return *(uint32_t*)&h;
}
__device__ __forceinline__ uint32_t ex2h2(uint32_t x) {
    uint32_t r;
    asm("ex2.approx.f16x2 %0, %1;" : "=r"(r) : "r"(x));
    return r;
}
__device__ __forceinline__ uint32_t hmul2u(uint32_t a, uint32_t b) {
    uint32_t r;
    asm("mul.rn.f16x2 %0, %1, %2;" : "=r"(r) : "r"(a), "r"(b));
    return r;
}
__device__ __forceinline__ float2 h2f2(uint32_t x) {
    __half2 h = *(__half2*)&x;
    return __half22float2(h);
}

// ---------------------------------------------------------------------------
// prep kernel: conv_x (32B/thread) + conv_w + zero fused
// blocks [0,8192): x; [8192,8576): W; [8576,9608): zero
// ---------------------------------------------------------------------------
__global__ __launch_bounds__(256) void prep_kernel(
    const float* __restrict__ x,
    const float* __restrict__ Wk, const float* __restrict__ Wq, const float* __restrict__ Wv,
    float* __restrict__ out)
{
    int bid = blockIdx.x;
    if (bid < 8192) {
        size_t i = ((size_t)bid*256 + threadIdx.x)*8;
        float4 v0 = *(const float4*)(x + i);
        float4 v1 = *(const float4*)(x + i + 4);
        uint4 h = make_uint4(packh2(v0.x, v0.y), packh2(v0.z, v0.w),
                             packh2(v1.x, v1.y), packh2(v1.z, v1.w));
        *(uint4*)(g_x + i) = h;
    } else if (bid < 8576) {
        int wb = bid - 8192;
        int w = wb >> 7, inner = wb & 127;
        const float* W = (w == 0) ? Wq : (w == 1) ? Wk : Wv;
        size_t i = ((size_t)inner*256 + threadIdx.x)*4;
        float4 v = *(const float4*)(W + i);
        *(uint2*)(g_w + (size_t)w*EMBED*HEAD + i) =
            make_uint2(packh2(v.x, v.y), packh2(v.z, v.w));
    } else {
        int zb = bid - 8576;
        float4 z = make_float4(0.f, 0.f, 0.f, 0.f);
        if (zb < 1024) {
            size_t i4 = (size_t)zb*256 + threadIdx.x;
            int b = (int)(i4 >> 16);
            int rem = (int)(i4 & 65535);
            *(float4*)(out + ((size_t)b*SEQ + 2048)*HEAD + (size_t)rem*4) = z;
        } else {
            int i4 = (zb - 1024)*256 + threadIdx.x;
            int b = i4 >> 9;
            int rem = i4 & 511;
            *(float4*)(g_l + (size_t)b*SEQ + 2048 + rem*4) = z;
        }
    }
}

__global__ __launch_bounds__(256) void norm_kernel(float* __restrict__ out)
{
    size_t i4 = (size_t)blockIdx.x*256 + threadIdx.x;
    int b = (int)(i4 >> 16);
    int rem = (int)(i4 & 65535);
    int row = b*SEQ + 2048 + (rem >> 5);
    float inv = 1.f / g_l[row];
    float* p = out + ((size_t)b*SEQ + 2048)*HEAD + (size_t)rem*4;
    float4 v = *(float4*)p;
    v.x *= inv; v.y *= inv; v.z *= inv; v.w *= inv;
    *(float4*)p = v;
}

// ---------------------------------------------------------------------------
// Projection GEMM (unchanged from R13): N-split, 768 CTAs, 2-stage ring,
// 3 CTAs/SM. stage = X 16K | W 8K; 2 stages = 48KB.
// ---------------------------------------------------------------------------
#define PJ_STAGE 24576
#define PJ_SMEM  (2*PJ_STAGE)

__global__ __launch_bounds__(256, 3) void proj_kernel()
{
    extern __shared__ char sm[];
    const uint32_t smb = smem_u32(sm);
    const int tid = threadIdx.x, wid = tid >> 5, l = tid & 31;
    const int w = blockIdx.x;
    const int row0 = blockIdx.y * 128;
    const int cz = blockIdx.z;
    const int rg = wid & 3;
    const int ch = wid >> 2;

    const __half* xg = g_x + (size_t)row0*EMBED;
    const __half* wg = g_w + (size_t)w*EMBED*HEAD + cz*64;

    auto load_stage = [&](int s, int k0) {
        uint32_t sb = smb + s*PJ_STAGE;
        #pragma unroll
        for (int i = 0; i < 4; i++) {
            int f = i*256 + tid;
            int r = f >> 3, c = f & 7;
            cpa(sb + sidx(r, c*16, 128), xg + (size_t)r*EMBED + k0 + c*8);
        }
        #pragma unroll
        for (int i = 0; i < 2; i++) {
            int f = i*256 + tid;
            int r = f >> 3, c = f & 7;
            cpa(sb + 16384 + sidx(r, c*16, 128), wg + (size_t)(k0 + r)*HEAD + c*8);
        }
        CP_COMMIT();
    };

    float acc[2][4][4];
    #pragma unroll
    for (int m = 0; m < 2; m++)
        #pragma unroll
        for (int n = 0; n < 4; n++)
            #pragma unroll
            for (int j = 0; j < 4; j++) acc[m][n][j] = 0.f;

    load_stage(0, 0);

    for (int chk = 0; chk < 16; chk++) {
        CP_WAIT0();
        __syncthreads();
        if (chk + 1 < 16) load_stage((chk + 1) & 1, (chk + 1)*64);

        uint32_t sb = smb + (chk & 1)*PJ_STAGE;
        #pragma unroll
        for (int ks = 0; ks < 4; ks++) {
            uint32_t ah[2][4];
            #pragma unroll
            for (int m = 0; m < 2; m++) {
                uint32_t aoff = sidx(rg*32 + m*16 + (l & 15), ks*32 + ((l >> 4) << 4), 128);
                ldsm4(ah[m], sb + aoff);
            }
            #pragma unroll
            for (int p = 0; p < 2; p++) {
                uint32_t bh[4];
                uint32_t boff = sidx(ks*16 + (l & 15),
                                     ch*64 + p*32 + ((l >> 4) & 1)*16, 128);
                ldsm4t(bh, sb + 16384 + boff);
                #pragma unroll
                for (int m = 0; m < 2; m++) {
                    mma16816(acc[m][p*2],   ah[m], bh);
                    mma16816(acc[m][p*2+1], ah[m], bh + 2);
                }
            }
        }
    }

    __half* dst = (w == 0) ? g_q : (w == 1) ? g_k : g_v;
    const float osc = (w == 0) ? QSCALE : 1.0f;
    #pragma unroll
    for (int m = 0; m < 2; m++) {
        const int g0 = row0 + rg*32 + m*16 + (l >> 2);
        const int cb = cz*64 + ch*32 + (l & 3)*2;
        #pragma unroll
        for (int nt = 0; nt < 4; nt++) {
            *(uint32_t*)(dst + (size_t)g0*HEAD + cb + nt*8) =
                packh2(acc[m][nt][0]*osc, acc[m][nt][1]*osc);
            *(uint32_t*)(dst + (size_t)(g0 + 8)*HEAD + cb + nt*8) =
                packh2(acc[m][nt][2]*osc, acc[m][nt][3]*osc);
        }
    }
}

// ---------------------------------------------------------------------------
// Flash attention: 128-query CTA (8 warps x 16q), 64-key tiles processed as
// two 32-key halves (register footprint == R12). No cross-warp O reduction.
// 2-stage KV ring, 2 CTAs/SM. smem: Q 32K | 2 x {K 16K, V 16K} = 96KB.
// ---------------------------------------------------------------------------
#define AT_KV0   32768
#define AT_STAGE 32768
#define AT_SMEM  (AT_KV0 + 2*AT_STAGE)
#define CHUNK    32
#define H2ONE    0x3C00u

__global__ __launch_bounds__(256, 2) void attn_kernel(float* __restrict__ out)
{
    const int qt = 31 - blockIdx.x;            // heavy q-tiles first
    const int c  = blockIdx.y;
    const int n_kt = 2*qt + 2;
    const int t0 = c*CHUNK;
    const int t1 = min(t0 + CHUNK, n_kt);
    if (t0 >= t1) return;

    extern __shared__ char sm[];
    const uint32_t smb = smem_u32(sm);
    const int tid = threadIdx.x, wid = tid >> 5, l = tid & 31;
    const int b   = blockIdx.z;
    const int q0  = qt*128;
    const int wq  = wid*16;
    const bool single = (c == 0) && (n_kt <= CHUNK);
    const int n = t1 - t0;

    // Q tile [128 x 128] into smem (group with KV t0)
    {
        const __half* qg = g_q + ((size_t)b*SEQ + q0)*HEAD;
        #pragma unroll
        for (int i = 0; i < 8; i++) {
            int f = i*256 + tid;
            int r = f >> 4, cc = f & 15;
            cpa(smb + sidx(r, cc*16, 256), qg + (size_t)r*HEAD + cc*8);
        }
    }

    auto load_kv = [&](int s, int t) {
        uint32_t sb = smb + AT_KV0 + s*AT_STAGE;
        const size_t base = ((size_t)b*SEQ + t*64)*HEAD;
        #pragma unroll
        for (int i = 0; i < 4; i++) {
            int f = i*256 + tid;
            int r = f >> 4, cc = f & 15;
            uint32_t d = sb + sidx(r, cc*16, 256);
            const size_t g = base + (size_t)r*HEAD + cc*8;
            cpa(d,         g_k + g);
            cpa(d + 16384, g_v + g);
        }
        CP_COMMIT();
    };

    load_kv(0, t0);    // commits Q + KV(t0)
    CP_WAIT0();
    __syncthreads();

    // hoist Q A-fragments (tile-invariant)
    uint32_t aq[8][4];
    #pragma unroll
    for (int ks = 0; ks < 8; ks++) {
        uint32_t aoff = sidx(wq + (l & 15), ks*32 + ((l >> 4) << 4), 256);
        ldsm4(aq[ks], smb + aoff);
    }

    float o[16][4];
    #pragma unroll
    for (int nn = 0; nn < 16; nn++)
        #pragma unroll
        for (int j = 0; j < 4; j++) o[nn][j] = 0.f;
    float lsum0 = 0.f, lsum1 = 0.f;

    const int lq = q0 + wq + (l >> 2);

    for (int t = t0; t < t1; t++) {
        const int idx = t - t0;
        if (idx + 1 < n) load_kv((idx + 1) & 1, t + 1);

        uint32_t sb = smb + AT_KV0 + (idx & 1)*AT_STAGE;
        const bool diag = (t >= 2*qt);

        #pragma unroll
        for (int hh = 0; hh < 2; hh++) {
            // ---- scores for 32 keys (fp16 accum) ----
            uint32_t sd[4][2];
            #pragma unroll
            for (int nn = 0; nn < 4; nn++) { sd[nn][0] = 0u; sd[nn][1] = 0u; }

            #pragma unroll
            for (int ks = 0; ks < 8; ks++) {
                #pragma unroll
                for (int ntp = 0; ntp < 2; ntp++) {
                    uint32_t bh[4];
                    uint32_t boff = sidx(hh*32 + (ntp*2 + ((l >> 4) & 1))*8 + (l & 7),
                                         ks*32 + ((l >> 3) & 1)*16, 256);
                    ldsm4(bh, sb + boff);
                    mma16816h(sd[ntp*2],   aq[ks], bh);
                    mma16816h(sd[ntp*2+1], aq[ks], bh + 2);
                }
            }

            // ---- p = ex2(s), causal mask, l ----
            uint32_t Ph[4][2];
            #pragma unroll
            for (int nt = 0; nt < 4; nt++) {
                uint32_t e0 = ex2h2(sd[nt][0]);
                uint32_t e1 = ex2h2(sd[nt][1]);
                if (diag) {
                    int kc = t*64 + hh*32 + nt*8 + (l & 3)*2;
                    uint32_t m0 = ((kc <= lq)     ? H2ONE : 0u) | ((kc + 1 <= lq)     ? (H2ONE << 16) : 0u);
                    uint32_t m1 = ((kc <= lq + 8) ? H2ONE : 0u) | ((kc + 1 <= lq + 8) ? (H2ONE << 16) : 0u);
                    e0 = hmul2u(e0, m0);
                    e1 = hmul2u(e1, m1);
                }
                Ph[nt][0] = e0; Ph[nt][1] = e1;
                float2 f0 = h2f2(e0), f1 = h2f2(e1);
                lsum0 += f0.x + f0.y;
                lsum1 += f1.x + f1.y;
            }

            // ---- O += P * V over these 32 keys ----
            #pragma unroll
            for (int ks = 0; ks < 2; ks++) {
                uint32_t ahh[4] = {Ph[2*ks][0], Ph[2*ks][1], Ph[2*ks+1][0], Ph[2*ks+1][1]};
                #pragma unroll
                for (int ntp = 0; ntp < 8; ntp++) {
                    uint32_t bh[4];
                    uint32_t boff = sidx(hh*32 + ks*16 + (l & 15),
                                         ntp*32 + ((l >> 4) & 1)*16, 256);
                    ldsm4t(bh, sb + 16384 + boff);
                    mma16816(o[ntp*2],   ahh, bh);
                    mma16816(o[ntp*2+1], ahh, bh + 2);
                }
            }
        }

        if (idx + 1 < n) { CP_WAIT0(); __syncthreads(); }
    }

    // ---- epilogue: warp-local l reduction, direct store / atomics ----
    lsum0 += __shfl_xor_sync(0xffffffffu, lsum0, 1);
    lsum0 += __shfl_xor_sync(0xffffffffu, lsum0, 2);
    lsum1 += __shfl_xor_sync(0xffffffffu, lsum1, 1);
    lsum1 += __shfl_xor_sync(0xffffffffu, lsum1, 2);

    const int row0g = q0 + wq + (l >> 2);
    const int cb = (l & 3)*2;
    float* og = out + ((size_t)b*SEQ + row0g)*HEAD;

    if (single) {
        const float inv0 = 1.f / lsum0;
        const float inv1 = 1.f / lsum1;
        #pragma unroll
        for (int nt = 0; nt < 16; nt++) {
            *(float2*)(og + nt*8 + cb) = make_float2(o[nt][0]*inv0, o[nt][1]*inv0);
            *(float2*)(og + (size_t)8*HEAD + nt*8 + cb) = make_float2(o[nt][2]*inv1, o[nt][3]*inv1);
        }
    } else {
        #pragma unroll
        for (int nt = 0; nt < 16; nt++) {
            atomicAdd(og + nt*8 + cb,     o[nt][0]);
            atomicAdd(og + nt*8 + cb + 1, o[nt][1]);
            atomicAdd(og + (size_t)8*HEAD + nt*8 + cb,     o[nt][2]);
            atomicAdd(og + (size_t)8*HEAD + nt*8 + cb + 1, o[nt][3]);
        }
        if ((l & 3) == 0) {
            atomicAdd(g_l + b*SEQ + row0g,     lsum0);
            atomicAdd(g_l + b*SEQ + row0g + 8, lsum1);
        }
    }
}

// ---------------------------------------------------------------------------
extern "C" void kernel_launch(void* const* d_in, const int* in_sizes, int n_in,
                              void* d_out, int out_size)
{
    const float* x  = (const float*)d_in[0];
    const float* Wk = (const float*)d_in[1];
    const float* Wq = (const float*)d_in[2];
    const float* Wv = (const float*)d_in[3];
    float* out = (float*)d_out;

    cudaFuncSetAttribute(proj_kernel, cudaFuncAttributeMaxDynamicSharedMemorySize, PJ_SMEM);
    cudaFuncSetAttribute(attn_kernel, cudaFuncAttributeMaxDynamicSharedMemorySize, AT_SMEM);

    prep_kernel<<<9608, 256>>>(x, Wk, Wq, Wv, out);
    proj_kernel<<<dim3(3, BS/128, 2), 256, PJ_SMEM>>>();
    attn_kernel<<<dim3(SEQ/128, 2, BATCH), 256, AT_SMEM>>>(out);
    norm_kernel<<<1024, 256>>>(out);
}

// round 15
// speedup vs baseline: 1.1573x; 1.1573x over previous
#include <cuda_runtime.h>
#include <cuda_fp16.h>
#include <cstdint>

#define EMBED 1024
#define HEAD  128
#define BATCH 4
#define SEQ   4096
#define BS    (BATCH*SEQ)
#define QSCALE 0.04508422f   // (1/sqrt(1024)) * log2(e)

// ---------------------------------------------------------------------------
// Global scratch (q prescaled by QSCALE at proj epilogue)
// ---------------------------------------------------------------------------
__device__ __align__(256) __half g_x[BS*EMBED];
__device__ __align__(256) __half g_w[3*EMBED*HEAD];
__device__ __align__(256) __half g_q[BS*HEAD], g_k[BS*HEAD], g_v[BS*HEAD];
__device__ __align__(256) float g_l[BS];

// ---------------------------------------------------------------------------
// helpers
// ---------------------------------------------------------------------------
__device__ __forceinline__ uint32_t smem_u32(const void* p) {
    uint32_t a;
    asm("{ .reg .u64 t; cvta.to.shared.u64 t, %1; cvt.u32.u64 %0, t; }" : "=r"(a) : "l"(p));
    return a;
}
__device__ __forceinline__ uint32_t sidx(int row, int cb, int rb) {
    return (uint32_t)(row*rb + ((((cb >> 4) ^ (row & 7)) << 4) | (cb & 15)));
}
__device__ __forceinline__ void cpa(uint32_t d, const void* s) {
    asm volatile("cp.async.cg.shared.global [%0], [%1], 16;" :: "r"(d), "l"(s));
}
#define CP_COMMIT() asm volatile("cp.async.commit_group;" ::: "memory")
#define CP_WAIT0()  asm volatile("cp.async.wait_group 0;" ::: "memory")
#define CP_WAIT1()  asm volatile("cp.async.wait_group 1;" ::: "memory")
#define CP_WAIT2()  asm volatile("cp.async.wait_group 2;" ::: "memory")

__device__ __forceinline__ void ldsm4(uint32_t* r, uint32_t a) {
    asm volatile("ldmatrix.sync.aligned.m8n8.x4.shared.b16 {%0,%1,%2,%3}, [%4];"
        : "=r"(r[0]), "=r"(r[1]), "=r"(r[2]), "=r"(r[3]) : "r"(a));
}
__device__ __forceinline__ void ldsm4t(uint32_t* r, uint32_t a) {
    asm volatile("ldmatrix.sync.aligned.m8n8.x4.trans.shared.b16 {%0,%1,%2,%3}, [%4];"
        : "=r"(r[0]), "=r"(r[1]), "=r"(r[2]), "=r"(r[3]) : "r"(a));
}
__device__ __forceinline__ void mma16816(float* d, const uint32_t* a, const uint32_t* b) {
    asm volatile("mma.sync.aligned.m16n8k16.row.col.f32.f16.f16.f32 "
        "{%0,%1,%2,%3}, {%4,%5,%6,%7}, {%8,%9}, {%0,%1,%2,%3};"
        : "+f"(d[0]), "+f"(d[1]), "+f"(d[2]), "+f"(d[3])
        : "r"(a[0]), "r"(a[1]), "r"(a[2]), "r"(a[3]), "r"(b[0]), "r"(b[1]));
}
__device__ __forceinline__ void mma16816h(uint32_t* d, const uint32_t* a, const uint32_t* b) {
    asm volatile("mma.sync.aligned.m16n8k16.row.col.f16.f16.f16.f16 "
        "{%0,%1}, {%2,%3,%4,%5}, {%6,%7}, {%0,%1};"
        : "+r"(d[0]), "+r"(d[1])
        : "r"(a[0]), "r"(a[1]), "r"(a[2]), "r"(a[3]), "r"(b[0]), "r"(b[1]));
}
__device__ __forceinline__ uint32_t packh2(float a, float b) {
    __half2 h = __floats2half2_rn(a, b);
    return *(uint32_t*)&h;
}
__device__ __forceinline__ uint32_t ex2h2(uint32_t x) {
    uint32_t r;
    asm("ex2.approx.f16x2 %0, %1;" : "=r"(r) : "r"(x));
    return r;
}
__device__ __forceinline__ uint32_t hmul2u(uint32_t a, uint32_t b) {
    uint32_t r;
    asm("mul.rn.f16x2 %0, %1, %2;" : "=r"(r) : "r"(a), "r"(b));
    return r;
}
__device__ __forceinline__ float2 h2f2(uint32_t x) {
    __half2 h = *(__half2*)&x;
    return __half22float2(h);
}

// ---------------------------------------------------------------------------
// prep kernel: conv_x (32B/thread) + conv_w + zero fused
// blocks [0,8192): x; [8192,8576): W; [8576,9608): zero
// ---------------------------------------------------------------------------
__global__ __launch_bounds__(256) void prep_kernel(
    const float* __restrict__ x,
    const float* __restrict__ Wk, const float* __restrict__ Wq, const float* __restrict__ Wv,
    float* __restrict__ out)
{
    int bid = blockIdx.x;
    if (bid < 8192) {
        size_t i = ((size_t)bid*256 + threadIdx.x)*8;
        float4 v0 = *(const float4*)(x + i);
        float4 v1 = *(const float4*)(x + i + 4);
        uint4 h = make_uint4(packh2(v0.x, v0.y), packh2(v0.z, v0.w),
                             packh2(v1.x, v1.y), packh2(v1.z, v1.w));
        *(uint4*)(g_x + i) = h;
    } else if (bid < 8576) {
        int wb = bid - 8192;
        int w = wb >> 7, inner = wb & 127;
        const float* W = (w == 0) ? Wq : (w == 1) ? Wk : Wv;
        size_t i = ((size_t)inner*256 + threadIdx.x)*4;
        float4 v = *(const float4*)(W + i);
        *(uint2*)(g_w + (size_t)w*EMBED*HEAD + i) =
            make_uint2(packh2(v.x, v.y), packh2(v.z, v.w));
    } else {
        int zb = bid - 8576;
        float4 z = make_float4(0.f, 0.f, 0.f, 0.f);
        if (zb < 1024) {
            size_t i4 = (size_t)zb*256 + threadIdx.x;
            int b = (int)(i4 >> 16);
            int rem = (int)(i4 & 65535);
            *(float4*)(out + ((size_t)b*SEQ + 2048)*HEAD + (size_t)rem*4) = z;
        } else {
            int i4 = (zb - 1024)*256 + threadIdx.x;
            int b = i4 >> 9;
            int rem = i4 & 511;
            *(float4*)(g_l + (size_t)b*SEQ + 2048 + rem*4) = z;
        }
    }
}

__global__ __launch_bounds__(256) void norm_kernel(float* __restrict__ out)
{
    size_t i4 = (size_t)blockIdx.x*256 + threadIdx.x;
    int b = (int)(i4 >> 16);
    int rem = (int)(i4 & 65535);
    int row = b*SEQ + 2048 + (rem >> 5);
    float inv = 1.f / g_l[row];
    float* p = out + ((size_t)b*SEQ + 2048)*HEAD + (size_t)rem*4;
    float4 v = *(float4*)p;
    v.x *= inv; v.y *= inv; v.z *= inv; v.w *= inv;
    *(float4*)p = v;
}

// ---------------------------------------------------------------------------
// Projection GEMM (R13): N-split, 768 CTAs, 2-stage ring, 3 CTAs/SM.
// stage = X 16K | W 8K; 2 stages = 48KB.
// ---------------------------------------------------------------------------
#define PJ_STAGE 24576
#define PJ_SMEM  (2*PJ_STAGE)

__global__ __launch_bounds__(256, 3) void proj_kernel()
{
    extern __shared__ char sm[];
    const uint32_t smb = smem_u32(sm);
    const int tid = threadIdx.x, wid = tid >> 5, l = tid & 31;
    const int w = blockIdx.x;
    const int row0 = blockIdx.y * 128;
    const int cz = blockIdx.z;
    const int rg = wid & 3;
    const int ch = wid >> 2;

    const __half* xg = g_x + (size_t)row0*EMBED;
    const __half* wg = g_w + (size_t)w*EMBED*HEAD + cz*64;

    auto load_stage = [&](int s, int k0) {
        uint32_t sb = smb + s*PJ_STAGE;
        #pragma unroll
        for (int i = 0; i < 4; i++) {
            int f = i*256 + tid;
            int r = f >> 3, c = f & 7;
            cpa(sb + sidx(r, c*16, 128), xg + (size_t)r*EMBED + k0 + c*8);
        }
        #pragma unroll
        for (int i = 0; i < 2; i++) {
            int f = i*256 + tid;
            int r = f >> 3, c = f & 7;
            cpa(sb + 16384 + sidx(r, c*16, 128), wg + (size_t)(k0 + r)*HEAD + c*8);
        }
        CP_COMMIT();
    };

    float acc[2][4][4];
    #pragma unroll
    for (int m = 0; m < 2; m++)
        #pragma unroll
        for (int n = 0; n < 4; n++)
            #pragma unroll
            for (int j = 0; j < 4; j++) acc[m][n][j] = 0.f;

    load_stage(0, 0);

    for (int chk = 0; chk < 16; chk++) {
        CP_WAIT0();
        __syncthreads();
        if (chk + 1 < 16) load_stage((chk + 1) & 1, (chk + 1)*64);

        uint32_t sb = smb + (chk & 1)*PJ_STAGE;
        #pragma unroll
        for (int ks = 0; ks < 4; ks++) {
            uint32_t ah[2][4];
            #pragma unroll
            for (int m = 0; m < 2; m++) {
                uint32_t aoff = sidx(rg*32 + m*16 + (l & 15), ks*32 + ((l >> 4) << 4), 128);
                ldsm4(ah[m], sb + aoff);
            }
            #pragma unroll
            for (int p = 0; p < 2; p++) {
                uint32_t bh[4];
                uint32_t boff = sidx(ks*16 + (l & 15),
                                     ch*64 + p*32 + ((l >> 4) & 1)*16, 128);
                ldsm4t(bh, sb + 16384 + boff);
                #pragma unroll
                for (int m = 0; m < 2; m++) {
                    mma16816(acc[m][p*2],   ah[m], bh);
                    mma16816(acc[m][p*2+1], ah[m], bh + 2);
                }
            }
        }
    }

    __half* dst = (w == 0) ? g_q : (w == 1) ? g_k : g_v;
    const float osc = (w == 0) ? QSCALE : 1.0f;
    #pragma unroll
    for (int m = 0; m < 2; m++) {
        const int g0 = row0 + rg*32 + m*16 + (l >> 2);
        const int cb = cz*64 + ch*32 + (l & 3)*2;
        #pragma unroll
        for (int nt = 0; nt < 4; nt++) {
            *(uint32_t*)(dst + (size_t)g0*HEAD + cb + nt*8) =
                packh2(acc[m][nt][0]*osc, acc[m][nt][1]*osc);
            *(uint32_t*)(dst + (size_t)(g0 + 8)*HEAD + cb + nt*8) =
                packh2(acc[m][nt][2]*osc, acc[m][nt][3]*osc);
        }
    }
}

// ---------------------------------------------------------------------------
// Flash attention (R13 structure, CHUNK=28): 64-query CTA, 8 warps, key-split
// halves, Q frags hoisted, fp16-accum scores + ex2.f16x2, 3-stage KV ring,
// 2 CTAs/SM. smem: Q 16K | 3 x {K 16K, V 16K} = 112KB.
// ---------------------------------------------------------------------------
#define AT_KV0   16384
#define AT_STAGE 32768
#define AT_SMEM  (AT_KV0 + 3*AT_STAGE)
#define CHUNK    28
#define H2ONE    0x3C00u

__global__ __launch_bounds__(256, 2) void attn_kernel(float* __restrict__ out)
{
    const int qt = 63 - blockIdx.x;
    const int c  = blockIdx.y;
    const int t0 = c*CHUNK;
    const int t1 = min(t0 + CHUNK, qt + 1);
    if (t0 >= t1) return;

    extern __shared__ char sm[];
    const uint32_t smb = smem_u32(sm);
    const int tid = threadIdx.x, wid = tid >> 5, l = tid & 31;
    const int b   = blockIdx.z;
    const int q0  = qt*64;
    const int wq  = (wid & 3)*16;
    const int kh  = wid >> 2;
    const bool single = (c == 0) && (qt + 1 <= CHUNK);
    const int n = t1 - t0;

    {
        const __half* qg = g_q + ((size_t)b*SEQ + q0)*HEAD;
        #pragma unroll
        for (int i = 0; i < 4; i++) {
            int f = i*256 + tid;
            int r = f >> 4, cc = f & 15;
            cpa(smb + sidx(r, cc*16, 256), qg + (size_t)r*HEAD + cc*8);
        }
        CP_COMMIT();
    }

    auto load_kv = [&](int s, int t) {
        uint32_t sb = smb + AT_KV0 + s*AT_STAGE;
        const size_t base = ((size_t)b*SEQ + t*64)*HEAD;
        #pragma unroll
        for (int i = 0; i < 4; i++) {
            int f = i*256 + tid;
            int r = f >> 4, cc = f & 15;
            uint32_t d = sb + sidx(r, cc*16, 256);
            const size_t g = base + (size_t)r*HEAD + cc*8;
            cpa(d,         g_k + g);
            cpa(d + 16384, g_v + g);
        }
        CP_COMMIT();
    };

    load_kv(0, t0);
    if (n > 1) load_kv(1, t0 + 1);

    if (n > 1) CP_WAIT2(); else CP_WAIT1();
    __syncthreads();
    uint32_t aq[8][4];
    #pragma unroll
    for (int ks = 0; ks < 8; ks++) {
        uint32_t aoff = sidx(wq + (l & 15), ks*32 + ((l >> 4) << 4), 256);
        ldsm4(aq[ks], smb + aoff);
    }

    float o[16][4];
    #pragma unroll
    for (int nn = 0; nn < 16; nn++)
        #pragma unroll
        for (int j = 0; j < 4; j++) o[nn][j] = 0.f;
    float lsum0 = 0.f, lsum1 = 0.f;

    for (int t = t0; t < t1; t++) {
        const int idx = t - t0;
        if (idx < n - 1) CP_WAIT1(); else CP_WAIT0();
        __syncthreads();
        if (idx + 2 < n) load_kv((idx + 2) % 3, t + 2);

        uint32_t sb = smb + AT_KV0 + (idx % 3)*AT_STAGE;

        uint32_t sd[4][2];
        #pragma unroll
        for (int nn = 0; nn < 4; nn++) { sd[nn][0] = 0u; sd[nn][1] = 0u; }

        #pragma unroll
        for (int ks = 0; ks < 8; ks++) {
            #pragma unroll
            for (int ntp = 0; ntp < 2; ntp++) {
                uint32_t bh[4];
                uint32_t boff = sidx(kh*32 + (ntp*2 + ((l >> 4) & 1))*8 + (l & 7),
                                     ks*32 + ((l >> 3) & 1)*16, 256);
                ldsm4(bh, sb + boff);
                mma16816h(sd[ntp*2],   aq[ks], bh);
                mma16816h(sd[ntp*2+1], aq[ks], bh + 2);
            }
        }

        uint32_t Ph[4][2];
        const bool diag = (t == qt);
        const int lq = q0 + wq + (l >> 2);
        #pragma unroll
        for (int nt = 0; nt < 4; nt++) {
            uint32_t e0 = ex2h2(sd[nt][0]);
            uint32_t e1 = ex2h2(sd[nt][1]);
            if (diag) {
                int kc = t*64 + kh*32 + nt*8 + (l & 3)*2;
                uint32_t m0 = ((kc <= lq)     ? H2ONE : 0u) | ((kc + 1 <= lq)     ? (H2ONE << 16) : 0u);
                uint32_t m1 = ((kc <= lq + 8) ? H2ONE : 0u) | ((kc + 1 <= lq + 8) ? (H2ONE << 16) : 0u);
                e0 = hmul2u(e0, m0);
                e1 = hmul2u(e1, m1);
            }
            Ph[nt][0] = e0; Ph[nt][1] = e1;
            float2 f0 = h2f2(e0), f1 = h2f2(e1);
            lsum0 += f0.x + f0.y;
            lsum1 += f1.x + f1.y;
        }

        #pragma unroll
        for (int ks = 0; ks < 2; ks++) {
            uint32_t ahh[4] = {Ph[2*ks][0], Ph[2*ks][1], Ph[2*ks+1][0], Ph[2*ks+1][1]};
            #pragma unroll
            for (int ntp = 0; ntp < 8; ntp++) {
                uint32_t bh[4];
                uint32_t boff = sidx(kh*32 + ks*16 + (l & 15),
                                     ntp*32 + ((l >> 4) & 1)*16, 256);
                ldsm4t(bh, sb + 16384 + boff);
                mma16816(o[ntp*2],   ahh, bh);
                mma16816(o[ntp*2+1], ahh, bh + 2);
            }
        }
    }
    __syncthreads();

    if (wid >= 4) {
        float* red = (float*)(sm + AT_KV0) + ((size_t)((wid - 4)*32 + l))*64;
        #pragma unroll
        for (int nt = 0; nt < 16; nt++)
            *(float4*)(red + nt*4) = make_float4(o[nt][0], o[nt][1], o[nt][2], o[nt][3]);
        float* lred = (float*)(sm + AT_KV0 + 32768) + ((wid - 4)*32 + l)*2;
        lred[0] = lsum0; lred[1] = lsum1;
    }
    __syncthreads();
    if (wid < 4) {
        float* red = (float*)(sm + AT_KV0) + ((size_t)(wid*32 + l))*64;
        #pragma unroll
        for (int nt = 0; nt < 16; nt++) {
            float4 r = *(float4*)(red + nt*4);
            o[nt][0] += r.x; o[nt][1] += r.y; o[nt][2] += r.z; o[nt][3] += r.w;
        }
        float* lred = (float*)(sm + AT_KV0 + 32768) + (wid*32 + l)*2;
        lsum0 += lred[0]; lsum1 += lred[1];

        lsum0 += __shfl_xor_sync(0xffffffffu, lsum0, 1);
        lsum0 += __shfl_xor_sync(0xffffffffu, lsum0, 2);
        lsum1 += __shfl_xor_sync(0xffffffffu, lsum1, 1);
        lsum1 += __shfl_xor_sync(0xffffffffu, lsum1, 2);

        const int row0g = q0 + wq + (l >> 2);
        const int cb = (l & 3)*2;
        float* og = out + ((size_t)b*SEQ + row0g)*HEAD;

        if (single) {
            const float inv0 = 1.f / lsum0;
            const float inv1 = 1.f / lsum1;
            #pragma unroll
            for (int nt = 0; nt < 16; nt++) {
                *(float2*)(og + nt*8 + cb) = make_float2(o[nt][0]*inv0, o[nt][1]*inv0);
                *(float2*)(og + (size_t)8*HEAD + nt*8 + cb) = make_float2(o[nt][2]*inv1, o[nt][3]*inv1);
            }
            if ((l & 3) == 0 && qt + 1 > CHUNK) {   // not reachable; guard kept cheap
            }
        } else {
            #pragma unroll
            for (int nt = 0; nt < 16; nt++) {
                atomicAdd(og + nt*8 + cb,     o[nt][0]);
                atomicAdd(og + nt*8 + cb + 1, o[nt][1]);
                atomicAdd(og + (size_t)8*HEAD + nt*8 + cb,     o[nt][2]);
                atomicAdd(og + (size_t)8*HEAD + nt*8 + cb + 1, o[nt][3]);
            }
            if ((l & 3) == 0) {
                atomicAdd(g_l + b*SEQ + row0g,     lsum0);
                atomicAdd(g_l + b*SEQ + row0g + 8, lsum1);
            }
        }
    }
}

// ---------------------------------------------------------------------------
// norm covers rows whose q-tile spans multiple chunks: qt+1 > CHUNK
// -> qt >= CHUNK -> rows >= CHUNK*64. Zero likewise.
// With CHUNK=28: rows >= 1792.
// ---------------------------------------------------------------------------
#define MC_ROW0 (CHUNK*64)          // 1792
#define MC_ROWS (SEQ - MC_ROW0)     // 2304
#define MC_F4   (MC_ROWS*HEAD/4)    // 73728 float4 per batch

__global__ __launch_bounds__(256) void zero_mc_kernel(float* __restrict__ out)
{
    // grid: BATCH * (MC_F4/256) blocks for out, + BATCH*MC_ROWS/1024 for g_l
    int bid = blockIdx.x;
    float4 z = make_float4(0.f, 0.f, 0.f, 0.f);
    const int out_blocks = BATCH*MC_F4/256;      // 4*288 = 1152
    if (bid < out_blocks) {
        int per_b = MC_F4/256;                   // 288
        int b = bid / per_b;
        size_t rem = (size_t)(bid % per_b)*256 + threadIdx.x;
        *(float4*)(out + ((size_t)b*SEQ + MC_ROW0)*HEAD + rem*4) = z;
    } else {
        int zb = bid - out_blocks;               // 0..8 (9 blocks: 4*2304/1024)
        int i4 = zb*256 + threadIdx.x;
        if (i4 < BATCH*MC_ROWS/4) {
            int b = i4 / (MC_ROWS/4);
            int rem = i4 % (MC_ROWS/4);
            *(float4*)(g_l + (size_t)b*SEQ + MC_ROW0 + rem*4) = z;
        }
    }
}
__global__ __launch_bounds__(256) void norm_mc_kernel(float* __restrict__ out)
{
    size_t i4 = (size_t)blockIdx.x*256 + threadIdx.x;   // BATCH*MC_F4 total
    int per_b = MC_F4;
    int b = (int)(i4 / per_b);
    int rem = (int)(i4 % per_b);
    int row = b*SEQ + MC_ROW0 + (rem >> 5);
    float inv = 1.f / g_l[row];
    float* p = out + ((size_t)b*SEQ + MC_ROW0)*HEAD + (size_t)rem*4;
    float4 v = *(float4*)p;
    v.x *= inv; v.y *= inv; v.z *= inv; v.w *= inv;
    *(float4*)p = v;
}

// ---------------------------------------------------------------------------
extern "C" void kernel_launch(void* const* d_in, const int* in_sizes, int n_in,
                              void* d_out, int out_size)
{
    const float* x  = (const float*)d_in[0];
    const float* Wk = (const float*)d_in[1];
    const float* Wq = (const float*)d_in[2];
    const float* Wv = (const float*)d_in[3];
    float* out = (float*)d_out;

    cudaFuncSetAttribute(proj_kernel, cudaFuncAttributeMaxDynamicSharedMemorySize, PJ_SMEM);
    cudaFuncSetAttribute(attn_kernel, cudaFuncAttributeMaxDynamicSharedMemorySize, AT_SMEM);

    // prep covers conv_x + conv_w only (zero handled by zero_mc_kernel)
    prep_kernel<<<8576, 256>>>(x, Wk, Wq, Wv, out);
    zero_mc_kernel<<<BATCH*MC_F4/256 + 9, 256>>>(out);
    proj_kernel<<<dim3(3, BS/128, 2), 256, PJ_SMEM>>>();
    attn_kernel<<<dim3(64, (SEQ/64 + CHUNK - 1)/CHUNK, BATCH), 256, AT_SMEM>>>(out);
    norm_mc_kernel<<<BATCH*MC_F4/256, 256>>>(out);
}

// round 16
// speedup vs baseline: 1.1922x; 1.0302x over previous
#include <cuda_runtime.h>
#include <cuda_fp16.h>
#include <cstdint>

#define EMBED 1024
#define HEAD  128
#define BATCH 4
#define SEQ   4096
#define BS    (BATCH*SEQ)
#define QSCALE 0.04508422f   // (1/sqrt(1024)) * log2(e)

// ---------------------------------------------------------------------------
// Global scratch (q prescaled by QSCALE at proj epilogue)
// ---------------------------------------------------------------------------
__device__ __align__(256) __half g_x[BS*EMBED];
__device__ __align__(256) __half g_w[3*EMBED*HEAD];
__device__ __align__(256) __half g_q[BS*HEAD], g_k[BS*HEAD], g_v[BS*HEAD];
__device__ __align__(256) float g_l[BS];

// ---------------------------------------------------------------------------
// helpers
// ---------------------------------------------------------------------------
__device__ __forceinline__ uint32_t smem_u32(const void* p) {
    uint32_t a;
    asm("{ .reg .u64 t; cvta.to.shared.u64 t, %1; cvt.u32.u64 %0, t; }" : "=r"(a) : "l"(p));
    return a;
}
__device__ __forceinline__ uint32_t sidx(int row, int cb, int rb) {
    return (uint32_t)(row*rb + ((((cb >> 4) ^ (row & 7)) << 4) | (cb & 15)));
}
__device__ __forceinline__ void cpa(uint32_t d, const void* s) {
    asm volatile("cp.async.cg.shared.global [%0], [%1], 16;" :: "r"(d), "l"(s));
}
#define CP_COMMIT() asm volatile("cp.async.commit_group;" ::: "memory")
#define CP_WAIT0()  asm volatile("cp.async.wait_group 0;" ::: "memory")
#define CP_WAIT1()  asm volatile("cp.async.wait_group 1;" ::: "memory")
#define CP_WAIT2()  asm volatile("cp.async.wait_group 2;" ::: "memory")

__device__ __forceinline__ void ldsm4(uint32_t* r, uint32_t a) {
    asm volatile("ldmatrix.sync.aligned.m8n8.x4.shared.b16 {%0,%1,%2,%3}, [%4];"
        : "=r"(r[0]), "=r"(r[1]), "=r"(r[2]), "=r"(r[3]) : "r"(a));
}
__device__ __forceinline__ void ldsm4t(uint32_t* r, uint32_t a) {
    asm volatile("ldmatrix.sync.aligned.m8n8.x4.trans.shared.b16 {%0,%1,%2,%3}, [%4];"
        : "=r"(r[0]), "=r"(r[1]), "=r"(r[2]), "=r"(r[3]) : "r"(a));
}
__device__ __forceinline__ void mma16816(float* d, const uint32_t* a, const uint32_t* b) {
    asm volatile("mma.sync.aligned.m16n8k16.row.col.f32.f16.f16.f32 "
        "{%0,%1,%2,%3}, {%4,%5,%6,%7}, {%8,%9}, {%0,%1,%2,%3};"
        : "+f"(d[0]), "+f"(d[1]), "+f"(d[2]), "+f"(d[3])
        : "r"(a[0]), "r"(a[1]), "r"(a[2]), "r"(a[3]), "r"(b[0]), "r"(b[1]));
}
__device__ __forceinline__ void mma16816h(uint32_t* d, const uint32_t* a, const uint32_t* b) {
    asm volatile("mma.sync.aligned.m16n8k16.row.col.f16.f16.f16.f16 "
        "{%0,%1}, {%2,%3,%4,%5}, {%6,%7}, {%0,%1};"
        : "+r"(d[0]), "+r"(d[1])
        : "r"(a[0]), "r"(a[1]), "r"(a[2]), "r"(a[3]), "r"(b[0]), "r"(b[1]));
}
__device__ __forceinline__ uint32_t packh2(float a, float b) {
    __half2 h = __floats2half2_rn(a, b);
    return *(uint32_t*)&h;
}
__device__ __forceinline__ uint32_t ex2h2(uint32_t x) {
    uint32_t r;
    asm("ex2.approx.f16x2 %0, %1;" : "=r"(r) : "r"(x));
    return r;
}
__device__ __forceinline__ uint32_t hmul2u(uint32_t a, uint32_t b) {
    uint32_t r;
    asm("mul.rn.f16x2 %0, %1, %2;" : "=r"(r) : "r"(a), "r"(b));
    return r;
}
__device__ __forceinline__ float2 h2f2(uint32_t x) {
    __half2 h = *(__half2*)&x;
    return __half22float2(h);
}

// ---------------------------------------------------------------------------
// prep kernel: conv_x (32B/thread) + conv_w. Zero in separate kernel.
// blocks [0,8192): x; [8192,8576): W
// ---------------------------------------------------------------------------
__global__ __launch_bounds__(256) void prep_kernel(
    const float* __restrict__ x,
    const float* __restrict__ Wk, const float* __restrict__ Wq, const float* __restrict__ Wv)
{
    int bid = blockIdx.x;
    if (bid < 8192) {
        size_t i = ((size_t)bid*256 + threadIdx.x)*8;
        float4 v0 = *(const float4*)(x + i);
        float4 v1 = *(const float4*)(x + i + 4);
        uint4 h = make_uint4(packh2(v0.x, v0.y), packh2(v0.z, v0.w),
                             packh2(v1.x, v1.y), packh2(v1.z, v1.w));
        *(uint4*)(g_x + i) = h;
    } else {
        int wb = bid - 8192;
        int w = wb >> 7, inner = wb & 127;
        const float* W = (w == 0) ? Wq : (w == 1) ? Wk : Wv;
        size_t i = ((size_t)inner*256 + threadIdx.x)*4;
        float4 v = *(const float4*)(W + i);
        *(uint2*)(g_w + (size_t)w*EMBED*HEAD + i) =
            make_uint2(packh2(v.x, v.y), packh2(v.z, v.w));
    }
}

// ---------------------------------------------------------------------------
// zero / normalize: rows q in [2048,4096) only (multi-chunk, atomic path)
// ---------------------------------------------------------------------------
__global__ __launch_bounds__(256) void zero_mc_kernel(float* __restrict__ out)
{
    int bid = blockIdx.x;
    float4 z = make_float4(0.f, 0.f, 0.f, 0.f);
    if (bid < 1024) {
        size_t i4 = (size_t)bid*256 + threadIdx.x;   // 65536 f4 per batch
        int b = (int)(i4 >> 16);
        int rem = (int)(i4 & 65535);
        *(float4*)(out + ((size_t)b*SEQ + 2048)*HEAD + (size_t)rem*4) = z;
    } else {
        int i4 = (bid - 1024)*256 + threadIdx.x;     // 2048 f4 for g_l
        int b = i4 >> 9;
        int rem = i4 & 511;
        *(float4*)(g_l + (size_t)b*SEQ + 2048 + rem*4) = z;
    }
}
__global__ __launch_bounds__(256) void norm_mc_kernel(float* __restrict__ out)
{
    size_t i4 = (size_t)blockIdx.x*256 + threadIdx.x;
    int b = (int)(i4 >> 16);
    int rem = (int)(i4 & 65535);
    int row = b*SEQ + 2048 + (rem >> 5);
    float inv = 1.f / g_l[row];
    float* p = out + ((size_t)b*SEQ + 2048)*HEAD + (size_t)rem*4;
    float4 v = *(float4*)p;
    v.x *= inv; v.y *= inv; v.z *= inv; v.w *= inv;
    *(float4*)p = v;
}

// ---------------------------------------------------------------------------
// Projection GEMM (R13): N-split, 768 CTAs, 2-stage ring, 3 CTAs/SM.
// stage = X 16K | W 8K; 2 stages = 48KB.
// ---------------------------------------------------------------------------
#define PJ_STAGE 24576
#define PJ_SMEM  (2*PJ_STAGE)

__global__ __launch_bounds__(256, 3) void proj_kernel()
{
    extern __shared__ char sm[];
    const uint32_t smb = smem_u32(sm);
    const int tid = threadIdx.x, wid = tid >> 5, l = tid & 31;
    const int w = blockIdx.x;
    const int row0 = blockIdx.y * 128;
    const int cz = blockIdx.z;
    const int rg = wid & 3;
    const int ch = wid >> 2;

    const __half* xg = g_x + (size_t)row0*EMBED;
    const __half* wg = g_w + (size_t)w*EMBED*HEAD + cz*64;

    auto load_stage = [&](int s, int k0) {
        uint32_t sb = smb + s*PJ_STAGE;
        #pragma unroll
        for (int i = 0; i < 4; i++) {
            int f = i*256 + tid;
            int r = f >> 3, c = f & 7;
            cpa(sb + sidx(r, c*16, 128), xg + (size_t)r*EMBED + k0 + c*8);
        }
        #pragma unroll
        for (int i = 0; i < 2; i++) {
            int f = i*256 + tid;
            int r = f >> 3, c = f & 7;
            cpa(sb + 16384 + sidx(r, c*16, 128), wg + (size_t)(k0 + r)*HEAD + c*8);
        }
        CP_COMMIT();
    };

    float acc[2][4][4];
    #pragma unroll
    for (int m = 0; m < 2; m++)
        #pragma unroll
        for (int n = 0; n < 4; n++)
            #pragma unroll
            for (int j = 0; j < 4; j++) acc[m][n][j] = 0.f;

    load_stage(0, 0);

    for (int chk = 0; chk < 16; chk++) {
        CP_WAIT0();
        __syncthreads();
        if (chk + 1 < 16) load_stage((chk + 1) & 1, (chk + 1)*64);

        uint32_t sb = smb + (chk & 1)*PJ_STAGE;
        #pragma unroll
        for (int ks = 0; ks < 4; ks++) {
            uint32_t ah[2][4];
            #pragma unroll
            for (int m = 0; m < 2; m++) {
                uint32_t aoff = sidx(rg*32 + m*16 + (l & 15), ks*32 + ((l >> 4) << 4), 128);
                ldsm4(ah[m], sb + aoff);
            }
            #pragma unroll
            for (int p = 0; p < 2; p++) {
                uint32_t bh[4];
                uint32_t boff = sidx(ks*16 + (l & 15),
                                     ch*64 + p*32 + ((l >> 4) & 1)*16, 128);
                ldsm4t(bh, sb + 16384 + boff);
                #pragma unroll
                for (int m = 0; m < 2; m++) {
                    mma16816(acc[m][p*2],   ah[m], bh);
                    mma16816(acc[m][p*2+1], ah[m], bh + 2);
                }
            }
        }
    }

    __half* dst = (w == 0) ? g_q : (w == 1) ? g_k : g_v;
    const float osc = (w == 0) ? QSCALE : 1.0f;
    #pragma unroll
    for (int m = 0; m < 2; m++) {
        const int g0 = row0 + rg*32 + m*16 + (l >> 2);
        const int cb = cz*64 + ch*32 + (l & 3)*2;
        #pragma unroll
        for (int nt = 0; nt < 4; nt++) {
            *(uint32_t*)(dst + (size_t)g0*HEAD + cb + nt*8) =
                packh2(acc[m][nt][0]*osc, acc[m][nt][1]*osc);
            *(uint32_t*)(dst + (size_t)(g0 + 8)*HEAD + cb + nt*8) =
                packh2(acc[m][nt][2]*osc, acc[m][nt][3]*osc);
        }
    }
}

// ---------------------------------------------------------------------------
// Flash attention (exact R13): 64-query CTA, 8 warps, key-split halves,
// Q frags hoisted, fp16-accum scores + ex2.f16x2, 3-stage KV ring, 2 CTAs/SM.
// CHUNK=32. smem: Q 16K | 3 x {K 16K, V 16K} = 112KB.
// ---------------------------------------------------------------------------
#define AT_KV0   16384
#define AT_STAGE 32768
#define AT_SMEM  (AT_KV0 + 3*AT_STAGE)
#define CHUNK    32
#define H2ONE    0x3C00u

__global__ __launch_bounds__(256, 2) void attn_kernel(float* __restrict__ out)
{
    const int qt = 63 - blockIdx.x;
    const int c  = blockIdx.y;
    const int t0 = c*CHUNK;
    const int t1 = min(t0 + CHUNK, qt + 1);
    if (t0 >= t1) return;

    extern __shared__ char sm[];
    const uint32_t smb = smem_u32(sm);
    const int tid = threadIdx.x, wid = tid >> 5, l = tid & 31;
    const int b   = blockIdx.z;
    const int q0  = qt*64;
    const int wq  = (wid & 3)*16;
    const int kh  = wid >> 2;
    const bool single = (c == 0) && (qt + 1 <= CHUNK);
    const int n = t1 - t0;

    {
        const __half* qg = g_q + ((size_t)b*SEQ + q0)*HEAD;
        #pragma unroll
        for (int i = 0; i < 4; i++) {
            int f = i*256 + tid;
            int r = f >> 4, cc = f & 15;
            cpa(smb + sidx(r, cc*16, 256), qg + (size_t)r*HEAD + cc*8);
        }
        CP_COMMIT();
    }

    auto load_kv = [&](int s, int t) {
        uint32_t sb = smb + AT_KV0 + s*AT_STAGE;
        const size_t base = ((size_t)b*SEQ + t*64)*HEAD;
        #pragma unroll
        for (int i = 0; i < 4; i++) {
            int f = i*256 + tid;
            int r = f >> 4, cc = f & 15;
            uint32_t d = sb + sidx(r, cc*16, 256);
            const size_t g = base + (size_t)r*HEAD + cc*8;
            cpa(d,         g_k + g);
            cpa(d + 16384, g_v + g);
        }
        CP_COMMIT();
    };

    load_kv(0, t0);
    if (n > 1) load_kv(1, t0 + 1);

    if (n > 1) CP_WAIT2(); else CP_WAIT1();
    __syncthreads();
    uint32_t aq[8][4];
    #pragma unroll
    for (int ks = 0; ks < 8; ks++) {
        uint32_t aoff = sidx(wq + (l & 15), ks*32 + ((l >> 4) << 4), 256);
        ldsm4(aq[ks], smb + aoff);
    }

    float o[16][4];
    #pragma unroll
    for (int nn = 0; nn < 16; nn++)
        #pragma unroll
        for (int j = 0; j < 4; j++) o[nn][j] = 0.f;
    float lsum0 = 0.f, lsum1 = 0.f;

    for (int t = t0; t < t1; t++) {
        const int idx = t - t0;
        if (idx < n - 1) CP_WAIT1(); else CP_WAIT0();
        __syncthreads();
        if (idx + 2 < n) load_kv((idx + 2) % 3, t + 2);

        uint32_t sb = smb + AT_KV0 + (idx % 3)*AT_STAGE;

        uint32_t sd[4][2];
        #pragma unroll
        for (int nn = 0; nn < 4; nn++) { sd[nn][0] = 0u; sd[nn][1] = 0u; }

        #pragma unroll
        for (int ks = 0; ks < 8; ks++) {
            #pragma unroll
            for (int ntp = 0; ntp < 2; ntp++) {
                uint32_t bh[4];
                uint32_t boff = sidx(kh*32 + (ntp*2 + ((l >> 4) & 1))*8 + (l & 7),
                                     ks*32 + ((l >> 3) & 1)*16, 256);
                ldsm4(bh, sb + boff);
                mma16816h(sd[ntp*2],   aq[ks], bh);
                mma16816h(sd[ntp*2+1], aq[ks], bh + 2);
            }
        }

        uint32_t Ph[4][2];
        const bool diag = (t == qt);
        const int lq = q0 + wq + (l >> 2);
        #pragma unroll
        for (int nt = 0; nt < 4; nt++) {
            uint32_t e0 = ex2h2(sd[nt][0]);
            uint32_t e1 = ex2h2(sd[nt][1]);
            if (diag) {
                int kc = t*64 + kh*32 + nt*8 + (l & 3)*2;
                uint32_t m0 = ((kc <= lq)     ? H2ONE : 0u) | ((kc + 1 <= lq)     ? (H2ONE << 16) : 0u);
                uint32_t m1 = ((kc <= lq + 8) ? H2ONE : 0u) | ((kc + 1 <= lq + 8) ? (H2ONE << 16) : 0u);
                e0 = hmul2u(e0, m0);
                e1 = hmul2u(e1, m1);
            }
            Ph[nt][0] = e0; Ph[nt][1] = e1;
            float2 f0 = h2f2(e0), f1 = h2f2(e1);
            lsum0 += f0.x + f0.y;
            lsum1 += f1.x + f1.y;
        }

        #pragma unroll
        for (int ks = 0; ks < 2; ks++) {
            uint32_t ahh[4] = {Ph[2*ks][0], Ph[2*ks][1], Ph[2*ks+1][0], Ph[2*ks+1][1]};
            #pragma unroll
            for (int ntp = 0; ntp < 8; ntp++) {
                uint32_t bh[4];
                uint32_t boff = sidx(kh*32 + ks*16 + (l & 15),
                                     ntp*32 + ((l >> 4) & 1)*16, 256);
                ldsm4t(bh, sb + 16384 + boff);
                mma16816(o[ntp*2],   ahh, bh);
                mma16816(o[ntp*2+1], ahh, bh + 2);
            }
        }
    }
    __syncthreads();

    if (wid >= 4) {
        float* red = (float*)(sm + AT_KV0) + ((size_t)((wid - 4)*32 + l))*64;
        #pragma unroll
        for (int nt = 0; nt < 16; nt++)
            *(float4*)(red + nt*4) = make_float4(o[nt][0], o[nt][1], o[nt][2], o[nt][3]);
        float* lred = (float*)(sm + AT_KV0 + 32768) + ((wid - 4)*32 + l)*2;
        lred[0] = lsum0; lred[1] = lsum1;
    }
    __syncthreads();
    if (wid < 4) {
        float* red = (float*)(sm + AT_KV0) + ((size_t)(wid*32 + l))*64;
        #pragma unroll
        for (int nt = 0; nt < 16; nt++) {
            float4 r = *(float4*)(red + nt*4);
            o[nt][0] += r.x; o[nt][1] += r.y; o[nt][2] += r.z; o[nt][3] += r.w;
        }
        float* lred = (float*)(sm + AT_KV0 + 32768) + (wid*32 + l)*2;
        lsum0 += lred[0]; lsum1 += lred[1];

        lsum0 += __shfl_xor_sync(0xffffffffu, lsum0, 1);
        lsum0 += __shfl_xor_sync(0xffffffffu, lsum0, 2);
        lsum1 += __shfl_xor_sync(0xffffffffu, lsum1, 1);
        lsum1 += __shfl_xor_sync(0xffffffffu, lsum1, 2);

        const int row0g = q0 + wq + (l >> 2);
        const int cb = (l & 3)*2;
        float* og = out + ((size_t)b*SEQ + row0g)*HEAD;

        if (single) {
            const float inv0 = 1.f / lsum0;
            const float inv1 = 1.f / lsum1;
            #pragma unroll
            for (int nt = 0; nt < 16; nt++) {
                *(float2*)(og + nt*8 + cb) = make_float2(o[nt][0]*inv0, o[nt][1]*inv0);
                *(float2*)(og + (size_t)8*HEAD + nt*8 + cb) = make_float2(o[nt][2]*inv1, o[nt][3]*inv1);
            }
        } else {
            #pragma unroll
            for (int nt = 0; nt < 16; nt++) {
                atomicAdd(og + nt*8 + cb,     o[nt][0]);
                atomicAdd(og + nt*8 + cb + 1, o[nt][1]);
                atomicAdd(og + (size_t)8*HEAD + nt*8 + cb,     o[nt][2]);
                atomicAdd(og + (size_t)8*HEAD + nt*8 + cb + 1, o[nt][3]);
            }
            if ((l & 3) == 0) {
                atomicAdd(g_l + b*SEQ + row0g,     lsum0);
                atomicAdd(g_l + b*SEQ + row0g + 8, lsum1);
            }
        }
    }
}

// ---------------------------------------------------------------------------
extern "C" void kernel_launch(void* const* d_in, const int* in_sizes, int n_in,
                              void* d_out, int out_size)
{
    const float* x  = (const float*)d_in[0];
    const float* Wk = (const float*)d_in[1];
    const float* Wq = (const float*)d_in[2];
    const float* Wv = (const float*)d_in[3];
    float* out = (float*)d_out;

    cudaFuncSetAttribute(proj_kernel, cudaFuncAttributeMaxDynamicSharedMemorySize, PJ_SMEM);
    cudaFuncSetAttribute(attn_kernel, cudaFuncAttributeMaxDynamicSharedMemorySize, AT_SMEM);

    prep_kernel<<<8576, 256>>>(x, Wk, Wq, Wv);
    zero_mc_kernel<<<1032, 256>>>(out);
    proj_kernel<<<dim3(3, BS/128, 2), 256, PJ_SMEM>>>();
    attn_kernel<<<dim3(64, (SEQ/64 + CHUNK - 1)/CHUNK, BATCH), 256, AT_SMEM>>>(out);
    norm_mc_kernel<<<1024, 256>>>(out);
}

// round 17
// speedup vs baseline: 1.3086x; 1.0976x over previous
#include <cuda_runtime.h>
#include <cuda_fp16.h>
#include <cstdint>

#define EMBED 1024
#define HEAD  128
#define BATCH 4
#define SEQ   4096
#define BS    (BATCH*SEQ)
#define QSCALE 0.04508422f   // (1/sqrt(1024)) * log2(e)

// ---------------------------------------------------------------------------
// Global scratch (q prescaled by QSCALE at proj epilogue)
// ---------------------------------------------------------------------------
__device__ __align__(256) __half g_x[BS*EMBED];
__device__ __align__(256) __half g_w[3*EMBED*HEAD];
__device__ __align__(256) __half g_q[BS*HEAD], g_k[BS*HEAD], g_v[BS*HEAD];
__device__ __align__(256) float g_l[BS];

// ---------------------------------------------------------------------------
// helpers
// ---------------------------------------------------------------------------
__device__ __forceinline__ uint32_t smem_u32(const void* p) {
    uint32_t a;
    asm("{ .reg .u64 t; cvta.to.shared.u64 t, %1; cvt.u32.u64 %0, t; }" : "=r"(a) : "l"(p));
    return a;
}
__device__ __forceinline__ uint32_t sidx(int row, int cb, int rb) {
    return (uint32_t)(row*rb + ((((cb >> 4) ^ (row & 7)) << 4) | (cb & 15)));
}
__device__ __forceinline__ void cpa(uint32_t d, const void* s) {
    asm volatile("cp.async.cg.shared.global [%0], [%1], 16;" :: "r"(d), "l"(s));
}
#define CP_COMMIT() asm volatile("cp.async.commit_group;" ::: "memory")
#define CP_WAIT0()  asm volatile("cp.async.wait_group 0;" ::: "memory")
#define CP_WAIT1()  asm volatile("cp.async.wait_group 1;" ::: "memory")
#define CP_WAIT2()  asm volatile("cp.async.wait_group 2;" ::: "memory")

__device__ __forceinline__ void ldsm4(uint32_t* r, uint32_t a) {
    asm volatile("ldmatrix.sync.aligned.m8n8.x4.shared.b16 {%0,%1,%2,%3}, [%4];"
        : "=r"(r[0]), "=r"(r[1]), "=r"(r[2]), "=r"(r[3]) : "r"(a));
}
__device__ __forceinline__ void ldsm4t(uint32_t* r, uint32_t a) {
    asm volatile("ldmatrix.sync.aligned.m8n8.x4.trans.shared.b16 {%0,%1,%2,%3}, [%4];"
        : "=r"(r[0]), "=r"(r[1]), "=r"(r[2]), "=r"(r[3]) : "r"(a));
}
__device__ __forceinline__ void mma16816(float* d, const uint32_t* a, const uint32_t* b) {
    asm volatile("mma.sync.aligned.m16n8k16.row.col.f32.f16.f16.f32 "
        "{%0,%1,%2,%3}, {%4,%5,%6,%7}, {%8,%9}, {%0,%1,%2,%3};"
        : "+f"(d[0]), "+f"(d[1]), "+f"(d[2]), "+f"(d[3])
        : "r"(a[0]), "r"(a[1]), "r"(a[2]), "r"(a[3]), "r"(b[0]), "r"(b[1]));
}
__device__ __forceinline__ void mma16816h(uint32_t* d, const uint32_t* a, const uint32_t* b) {
    asm volatile("mma.sync.aligned.m16n8k16.row.col.f16.f16.f16.f16 "
        "{%0,%1}, {%2,%3,%4,%5}, {%6,%7}, {%0,%1};"
        : "+r"(d[0]), "+r"(d[1])
        : "r"(a[0]), "r"(a[1]), "r"(a[2]), "r"(a[3]), "r"(b[0]), "r"(b[1]));
}
__device__ __forceinline__ uint32_t packh2(float a, float b) {
    __half2 h = __floats2half2_rn(a, b);
    return *(uint32_t*)&h;
}
__device__ __forceinline__ uint32_t ex2h2(uint32_t x) {
    uint32_t r;
    asm("ex2.approx.f16x2 %0, %1;" : "=r"(r) : "r"(x));
    return r;
}
__device__ __forceinline__ uint32_t hmul2u(uint32_t a, uint32_t b) {
    uint32_t r;
    asm("mul.rn.f16x2 %0, %1, %2;" : "=r"(r) : "r"(a), "r"(b));
    return r;
}
__device__ __forceinline__ float2 h2f2(uint32_t x) {
    __half2 h = *(__half2*)&x;
    return __half22float2(h);
}

// ---------------------------------------------------------------------------
// prep kernel: conv_x (32B/thread) + conv_w
// ---------------------------------------------------------------------------
__global__ __launch_bounds__(256) void prep_kernel(
    const float* __restrict__ x,
    const float* __restrict__ Wk, const float* __restrict__ Wq, const float* __restrict__ Wv)
{
    int bid = blockIdx.x;
    if (bid < 8192) {
        size_t i = ((size_t)bid*256 + threadIdx.x)*8;
        float4 v0 = *(const float4*)(x + i);
        float4 v1 = *(const float4*)(x + i + 4);
        uint4 h = make_uint4(packh2(v0.x, v0.y), packh2(v0.z, v0.w),
                             packh2(v1.x, v1.y), packh2(v1.z, v1.w));
        *(uint4*)(g_x + i) = h;
    } else {
        int wb = bid - 8192;
        int w = wb >> 7, inner = wb & 127;
        const float* W = (w == 0) ? Wq : (w == 1) ? Wk : Wv;
        size_t i = ((size_t)inner*256 + threadIdx.x)*4;
        float4 v = *(const float4*)(W + i);
        *(uint2*)(g_w + (size_t)w*EMBED*HEAD + i) =
            make_uint2(packh2(v.x, v.y), packh2(v.z, v.w));
    }
}

// ---------------------------------------------------------------------------
// zero / normalize: rows q in [2048,4096) only (multi-chunk, atomic path)
// ---------------------------------------------------------------------------
__global__ __launch_bounds__(256) void zero_mc_kernel(float* __restrict__ out)
{
    int bid = blockIdx.x;
    float4 z = make_float4(0.f, 0.f, 0.f, 0.f);
    if (bid < 1024) {
        size_t i4 = (size_t)bid*256 + threadIdx.x;
        int b = (int)(i4 >> 16);
        int rem = (int)(i4 & 65535);
        *(float4*)(out + ((size_t)b*SEQ + 2048)*HEAD + (size_t)rem*4) = z;
    } else {
        int i4 = (bid - 1024)*256 + threadIdx.x;
        int b = i4 >> 9;
        int rem = i4 & 511;
        *(float4*)(g_l + (size_t)b*SEQ + 2048 + rem*4) = z;
    }
}
__global__ __launch_bounds__(256) void norm_mc_kernel(float* __restrict__ out)
{
    size_t i4 = (size_t)blockIdx.x*256 + threadIdx.x;
    int b = (int)(i4 >> 16);
    int rem = (int)(i4 & 65535);
    int row = b*SEQ + 2048 + (rem >> 5);
    float inv = 1.f / g_l[row];
    float* p = out + ((size_t)b*SEQ + 2048)*HEAD + (size_t)rem*4;
    float4 v = *(float4*)p;
    v.x *= inv; v.y *= inv; v.z *= inv; v.w *= inv;
    *(float4*)p = v;
}

// ---------------------------------------------------------------------------
// Projection GEMM (R13): N-split, 768 CTAs, 2-stage ring, 3 CTAs/SM.
// ---------------------------------------------------------------------------
#define PJ_STAGE 24576
#define PJ_SMEM  (2*PJ_STAGE)

__global__ __launch_bounds__(256, 3) void proj_kernel()
{
    extern __shared__ char sm[];
    const uint32_t smb = smem_u32(sm);
    const int tid = threadIdx.x, wid = tid >> 5, l = tid & 31;
    const int w = blockIdx.x;
    const int row0 = blockIdx.y * 128;
    const int cz = blockIdx.z;
    const int rg = wid & 3;
    const int ch = wid >> 2;

    const __half* xg = g_x + (size_t)row0*EMBED;
    const __half* wg = g_w + (size_t)w*EMBED*HEAD + cz*64;

    auto load_stage = [&](int s, int k0) {
        uint32_t sb = smb + s*PJ_STAGE;
        #pragma unroll
        for (int i = 0; i < 4; i++) {
            int f = i*256 + tid;
            int r = f >> 3, c = f & 7;
            cpa(sb + sidx(r, c*16, 128), xg + (size_t)r*EMBED + k0 + c*8);
        }
        #pragma unroll
        for (int i = 0; i < 2; i++) {
            int f = i*256 + tid;
            int r = f >> 3, c = f & 7;
            cpa(sb + 16384 + sidx(r, c*16, 128), wg + (size_t)(k0 + r)*HEAD + c*8);
        }
        CP_COMMIT();
    };

    float acc[2][4][4];
    #pragma unroll
    for (int m = 0; m < 2; m++)
        #pragma unroll
        for (int n = 0; n < 4; n++)
            #pragma unroll
            for (int j = 0; j < 4; j++) acc[m][n][j] = 0.f;

    load_stage(0, 0);

    for (int chk = 0; chk < 16; chk++) {
        CP_WAIT0();
        __syncthreads();
        if (chk + 1 < 16) load_stage((chk + 1) & 1, (chk + 1)*64);

        uint32_t sb = smb + (chk & 1)*PJ_STAGE;
        #pragma unroll
        for (int ks = 0; ks < 4; ks++) {
            uint32_t ah[2][4];
            #pragma unroll
            for (int m = 0; m < 2; m++) {
                uint32_t aoff = sidx(rg*32 + m*16 + (l & 15), ks*32 + ((l >> 4) << 4), 128);
                ldsm4(ah[m], sb + aoff);
            }
            #pragma unroll
            for (int p = 0; p < 2; p++) {
                uint32_t bh[4];
                uint32_t boff = sidx(ks*16 + (l & 15),
                                     ch*64 + p*32 + ((l >> 4) & 1)*16, 128);
                ldsm4t(bh, sb + 16384 + boff);
                #pragma unroll
                for (int m = 0; m < 2; m++) {
                    mma16816(acc[m][p*2],   ah[m], bh);
                    mma16816(acc[m][p*2+1], ah[m], bh + 2);
                }
            }
        }
    }

    __half* dst = (w == 0) ? g_q : (w == 1) ? g_k : g_v;
    const float osc = (w == 0) ? QSCALE : 1.0f;
    #pragma unroll
    for (int m = 0; m < 2; m++) {
        const int g0 = row0 + rg*32 + m*16 + (l >> 2);
        const int cb = cz*64 + ch*32 + (l & 3)*2;
        #pragma unroll
        for (int nt = 0; nt < 4; nt++) {
            *(uint32_t*)(dst + (size_t)g0*HEAD + cb + nt*8) =
                packh2(acc[m][nt][0]*osc, acc[m][nt][1]*osc);
            *(uint32_t*)(dst + (size_t)(g0 + 8)*HEAD + cb + nt*8) =
                packh2(acc[m][nt][2]*osc, acc[m][nt][3]*osc);
        }
    }
}

// ---------------------------------------------------------------------------
// Flash attention (R13 body) with LPT block ordering: 384 non-empty work
// items mapped blockIdx.x -> (qt, c, b) in descending-work order.
// CHUNK=32. smem: Q 16K | 3 x {K 16K, V 16K} = 112KB. 2 CTAs/SM.
// ---------------------------------------------------------------------------
#define AT_KV0   16384
#define AT_STAGE 32768
#define AT_SMEM  (AT_KV0 + 3*AT_STAGE)
#define CHUNK    32
#define H2ONE    0x3C00u

__global__ __launch_bounds__(256, 2) void attn_kernel(float* __restrict__ out)
{
    // ---- LPT work-item decode: items sorted by descending tile count ----
    int idx = blockIdx.x;
    int b, c, qt;
    if (idx < 132) {                 // work 32: c0, qt 63..31
        c = 0; b = idx & 3; qt = 63 - (idx >> 2);
    } else {
        int j = idx - 132;
        if (j < 4) {                 // work 32: c1, qt 63
            c = 1; b = j; qt = 63;
        } else {
            j -= 4;                  // 0..247, works 31..1 alternating c1/c0
            int w = 31 - (j >> 3);
            int r = j & 7;
            b = r & 3;
            if (r < 4) { c = 1; qt = w + 31; }
            else       { c = 0; qt = w - 1; }
        }
    }

    const int t0 = c*CHUNK;
    const int t1 = min(t0 + CHUNK, qt + 1);

    extern __shared__ char sm[];
    const uint32_t smb = smem_u32(sm);
    const int tid = threadIdx.x, wid = tid >> 5, l = tid & 31;
    const int q0  = qt*64;
    const int wq  = (wid & 3)*16;
    const int kh  = wid >> 2;
    const bool single = (c == 0) && (qt + 1 <= CHUNK);
    const int n = t1 - t0;

    {
        const __half* qg = g_q + ((size_t)b*SEQ + q0)*HEAD;
        #pragma unroll
        for (int i = 0; i < 4; i++) {
            int f = i*256 + tid;
            int r = f >> 4, cc = f & 15;
            cpa(smb + sidx(r, cc*16, 256), qg + (size_t)r*HEAD + cc*8);
        }
        CP_COMMIT();
    }

    auto load_kv = [&](int s, int t) {
        uint32_t sb = smb + AT_KV0 + s*AT_STAGE;
        const size_t base = ((size_t)b*SEQ + t*64)*HEAD;
        #pragma unroll
        for (int i = 0; i < 4; i++) {
            int f = i*256 + tid;
            int r = f >> 4, cc = f & 15;
            uint32_t d = sb + sidx(r, cc*16, 256);
            const size_t g = base + (size_t)r*HEAD + cc*8;
            cpa(d,         g_k + g);
            cpa(d + 16384, g_v + g);
        }
        CP_COMMIT();
    };

    load_kv(0, t0);
    if (n > 1) load_kv(1, t0 + 1);

    if (n > 1) CP_WAIT2(); else CP_WAIT1();
    __syncthreads();
    uint32_t aq[8][4];
    #pragma unroll
    for (int ks = 0; ks < 8; ks++) {
        uint32_t aoff = sidx(wq + (l & 15), ks*32 + ((l >> 4) << 4), 256);
        ldsm4(aq[ks], smb + aoff);
    }

    float o[16][4];
    #pragma unroll
    for (int nn = 0; nn < 16; nn++)
        #pragma unroll
        for (int j = 0; j < 4; j++) o[nn][j] = 0.f;
    float lsum0 = 0.f, lsum1 = 0.f;

    for (int t = t0; t < t1; t++) {
        const int idx2 = t - t0;
        if (idx2 < n - 1) CP_WAIT1(); else CP_WAIT0();
        __syncthreads();
        if (idx2 + 2 < n) load_kv((idx2 + 2) % 3, t + 2);

        uint32_t sb = smb + AT_KV0 + (idx2 % 3)*AT_STAGE;

        uint32_t sd[4][2];
        #pragma unroll
        for (int nn = 0; nn < 4; nn++) { sd[nn][0] = 0u; sd[nn][1] = 0u; }

        #pragma unroll
        for (int ks = 0; ks < 8; ks++) {
            #pragma unroll
            for (int ntp = 0; ntp < 2; ntp++) {
                uint32_t bh[4];
                uint32_t boff = sidx(kh*32 + (ntp*2 + ((l >> 4) & 1))*8 + (l & 7),
                                     ks*32 + ((l >> 3) & 1)*16, 256);
                ldsm4(bh, sb + boff);
                mma16816h(sd[ntp*2],   aq[ks], bh);
                mma16816h(sd[ntp*2+1], aq[ks], bh + 2);
            }
        }

        uint32_t Ph[4][2];
        const bool diag = (t == qt);
        const int lq = q0 + wq + (l >> 2);
        #pragma unroll
        for (int nt = 0; nt < 4; nt++) {
            uint32_t e0 = ex2h2(sd[nt][0]);
            uint32_t e1 = ex2h2(sd[nt][1]);
            if (diag) {
                int kc = t*64 + kh*32 + nt*8 + (l & 3)*2;
                uint32_t m0 = ((kc <= lq)     ? H2ONE : 0u) | ((kc + 1 <= lq)     ? (H2ONE << 16) : 0u);
                uint32_t m1 = ((kc <= lq + 8) ? H2ONE : 0u) | ((kc + 1 <= lq + 8) ? (H2ONE << 16) : 0u);
                e0 = hmul2u(e0, m0);
                e1 = hmul2u(e1, m1);
            }
            Ph[nt][0] = e0; Ph[nt][1] = e1;
            float2 f0 = h2f2(e0), f1 = h2f2(e1);
            lsum0 += f0.x + f0.y;
            lsum1 += f1.x + f1.y;
        }

        #pragma unroll
        for (int ks = 0; ks < 2; ks++) {
            uint32_t ahh[4] = {Ph[2*ks][0], Ph[2*ks][1], Ph[2*ks+1][0], Ph[2*ks+1][1]};
            #pragma unroll
            for (int ntp = 0; ntp < 8; ntp++) {
                uint32_t bh[4];
                uint32_t boff = sidx(kh*32 + ks*16 + (l & 15),
                                     ntp*32 + ((l >> 4) & 1)*16, 256);
                ldsm4t(bh, sb + 16384 + boff);
                mma16816(o[ntp*2],   ahh, bh);
                mma16816(o[ntp*2+1], ahh, bh + 2);
            }
        }
    }
    __syncthreads();

    if (wid >= 4) {
        float* red = (float*)(sm + AT_KV0) + ((size_t)((wid - 4)*32 + l))*64;
        #pragma unroll
        for (int nt = 0; nt < 16; nt++)
            *(float4*)(red + nt*4) = make_float4(o[nt][0], o[nt][1], o[nt][2], o[nt][3]);
        float* lred = (float*)(sm + AT_KV0 + 32768) + ((wid - 4)*32 + l)*2;
        lred[0] = lsum0; lred[1] = lsum1;
    }
    __syncthreads();
    if (wid < 4) {
        float* red = (float*)(sm + AT_KV0) + ((size_t)(wid*32 + l))*64;
        #pragma unroll
        for (int nt = 0; nt < 16; nt++) {
            float4 r = *(float4*)(red + nt*4);
            o[nt][0] += r.x; o[nt][1] += r.y; o[nt][2] += r.z; o[nt][3] += r.w;
        }
        float* lred = (float*)(sm + AT_KV0 + 32768) + (wid*32 + l)*2;
        lsum0 += lred[0]; lsum1 += lred[1];

        lsum0 += __shfl_xor_sync(0xffffffffu, lsum0, 1);
        lsum0 += __shfl_xor_sync(0xffffffffu, lsum0, 2);
        lsum1 += __shfl_xor_sync(0xffffffffu, lsum1, 1);
        lsum1 += __shfl_xor_sync(0xffffffffu, lsum1, 2);

        const int row0g = q0 + wq + (l >> 2);
        const int cb = (l & 3)*2;
        float* og = out + ((size_t)b*SEQ + row0g)*HEAD;

        if (single) {
            const float inv0 = 1.f / lsum0;
            const float inv1 = 1.f / lsum1;
            #pragma unroll
            for (int nt = 0; nt < 16; nt++) {
                *(float2*)(og + nt*8 + cb) = make_float2(o[nt][0]*inv0, o[nt][1]*inv0);
                *(float2*)(og + (size_t)8*HEAD + nt*8 + cb) = make_float2(o[nt][2]*inv1, o[nt][3]*inv1);
            }
        } else {
            #pragma unroll
            for (int nt = 0; nt < 16; nt++) {
                atomicAdd(og + nt*8 + cb,     o[nt][0]);
                atomicAdd(og + nt*8 + cb + 1, o[nt][1]);
                atomicAdd(og + (size_t)8*HEAD + nt*8 + cb,     o[nt][2]);
                atomicAdd(og + (size_t)8*HEAD + nt*8 + cb + 1, o[nt][3]);
            }
            if ((l & 3) == 0) {
                atomicAdd(g_l + b*SEQ + row0g,     lsum0);
                atomicAdd(g_l + b*SEQ + row0g + 8, lsum1);
            }
        }
    }
}

// ---------------------------------------------------------------------------
extern "C" void kernel_launch(void* const* d_in, const int* in_sizes, int n_in,
                              void* d_out, int out_size)
{
    const float* x  = (const float*)d_in[0];
    const float* Wk = (const float*)d_in[1];
    const float* Wq = (const float*)d_in[2];
    const float* Wv = (const float*)d_in[3];
    float* out = (float*)d_out;

    cudaFuncSetAttribute(proj_kernel, cudaFuncAttributeMaxDynamicSharedMemorySize, PJ_SMEM);
    cudaFuncSetAttribute(attn_kernel, cudaFuncAttributeMaxDynamicSharedMemorySize, AT_SMEM);

    prep_kernel<<<8576, 256>>>(x, Wk, Wq, Wv);
    zero_mc_kernel<<<1032, 256>>>(out);
    proj_kernel<<<dim3(3, BS/128, 2), 256, PJ_SMEM>>>();
    attn_kernel<<<384, 256, AT_SMEM>>>(out);
    norm_mc_kernel<<<1024, 256>>>(out);
}